// round 15
// baseline (speedup 1.0000x reference)
#include <cuda_runtime.h>
#include <math.h>

// RZ_50259707298063: y_re[s,b] = xr[s,b]*cos(phi_s) - xi[s,b]*sin(phi_s)
// phi_s = sum_i ( bit(s, nwires-1-i) ? +theta_i/2 : -theta_i/2 )
// Output = float32 real part (established round 7).
//
// R14: R10 structure (phase-table kernel + clean stream) was best; its
// stream ran 2 waves (grid=2048 @ 8 blocks/SM) paying ~1.2us wave
// transition. Single-wave stream: 1024 blocks, 2 float4-pairs per thread
// (split nvec/2 apart), 4 front-batched LDG.128.

#define MAX_STATES 65536   // up to 16 wires; 512 KB table

__device__ float2 g_phase[MAX_STATES];

__global__ void __launch_bounds__(256) phase_table_kernel(
    const float* __restrict__ angle, int nwires, int nstates)
{
    const int s = blockIdx.x * blockDim.x + threadIdx.x;
    if (s >= nstates) return;
    float phi = 0.0f;
    for (int i = 0; i < nwires; i++) {
        const float half = 0.5f * angle[i];
        phi += ((s >> (nwires - 1 - i)) & 1) ? half : -half;
    }
    float sn, cs;
    sincosf(phi, &sn, &cs);
    g_phase[s] = make_float2(cs, sn);
}

// Single-wave stream: each thread does float4s v and v+half.
__global__ void __launch_bounds__(256) rz_stream_1wave(
    const float4* __restrict__ xr,
    const float4* __restrict__ xi,
    float4* __restrict__ out,
    int log2_vpr, int half)
{
    const int T = gridDim.x * blockDim.x;
    for (int v = blockIdx.x * blockDim.x + threadIdx.x; v < half; v += T) {
        const int w = v + half;
        // Front-batched: 4 LDG.128 in flight.
        const float4 r0 = xr[v];
        const float4 r1 = xr[w];
        const float4 i0 = xi[v];
        const float4 i1 = xi[w];
        const float2 p0 = __ldg(&g_phase[v >> log2_vpr]);
        const float2 p1 = __ldg(&g_phase[w >> log2_vpr]);

        float4 o0, o1;
        o0.x = fmaf(r0.x, p0.x, -i0.x * p0.y);
        o0.y = fmaf(r0.y, p0.x, -i0.y * p0.y);
        o0.z = fmaf(r0.z, p0.x, -i0.z * p0.y);
        o0.w = fmaf(r0.w, p0.x, -i0.w * p0.y);
        o1.x = fmaf(r1.x, p1.x, -i1.x * p1.y);
        o1.y = fmaf(r1.y, p1.x, -i1.y * p1.y);
        o1.z = fmaf(r1.z, p1.x, -i1.z * p1.y);
        o1.w = fmaf(r1.w, p1.x, -i1.w * p1.y);

        out[v] = o0;
        out[w] = o1;
    }
}

// Generic fallback (proven correct round 7).
__global__ void __launch_bounds__(256) rz_real_scalar(
    const float* __restrict__ xr,
    const float* __restrict__ xi,
    const float* __restrict__ angle,
    int nwires, int batch, long n,
    float* __restrict__ out)
{
    const long stride = (long)gridDim.x * blockDim.x;
    for (long e = (long)blockIdx.x * blockDim.x + threadIdx.x; e < n; e += stride) {
        const long s = e / batch;
        float phi = 0.0f;
        for (int i = 0; i < nwires; i++) {
            const float half = 0.5f * __ldg(&angle[i]);
            phi += (((s >> (nwires - 1 - i)) & 1L) != 0) ? half : -half;
        }
        float sn, cs;
        sincosf(phi, &sn, &cs);
        out[e] = fmaf(xr[e], cs, -xi[e] * sn);
    }
}

extern "C" void kernel_launch(void* const* d_in, const int* in_sizes, int n_in,
                              void* d_out, int out_size) {
    if (n_in < 3 || d_out == nullptr) return;

    // angle = smallest buffer; remaining two equal-size buffers, in index
    // order, are x_real then x_imag.
    int ai = 0;
    for (int i = 1; i < n_in; i++)
        if (in_sizes[i] < in_sizes[ai]) ai = i;

    const float* angle = (const float*)d_in[ai];
    const float* xr = nullptr;
    const float* xi = nullptr;
    long nelem = 0;
    for (int i = 0; i < n_in; i++) {
        if (i == ai) continue;
        if (xr == nullptr) { xr = (const float*)d_in[i]; nelem = in_sizes[i]; }
        else if (xi == nullptr && in_sizes[i] == (int)nelem)
            xi = (const float*)d_in[i];
    }
    if (!angle || !xr || !xi || nelem <= 0) return;

    int nwires = in_sizes[ai];
    if (nwires > 20) { nwires /= 4; nelem /= 4; }   // byte-count hedge
    if (nwires < 1 || nwires > 20) return;

    const long nstates = 1L << nwires;
    int batch = (int)(nelem / nstates);
    if (batch <= 0) batch = 1;

    // Output budget in floats (real part only).
    long n = nelem;
    if ((long)out_size < n) n = (long)out_size;

    const int vpr = batch / 4;
    int log2_vpr = 0;
    while ((1 << log2_vpr) < vpr && log2_vpr < 30) log2_vpr++;

    const bool fused_ok =
        (n == nelem) && (batch % 4 == 0) && ((1 << log2_vpr) == vpr) &&
        (nstates <= MAX_STATES) && (n % 8 == 0) && (n / 4 < (1L << 31));

    if (fused_ok) {
        phase_table_kernel<<<(int)((nstates + 255) / 256), 256>>>(
            angle, nwires, (int)nstates);
        const int nvec = (int)(n / 4);
        const int half = nvec / 2;
        // 1024 blocks x 256 threads: <=7 blocks/SM -> one wave.
        rz_stream_1wave<<<1024, 256>>>(
            (const float4*)xr, (const float4*)xi, (float4*)d_out,
            log2_vpr, half);
    } else {
        rz_real_scalar<<<2048, 256>>>(xr, xi, angle, nwires, batch, n,
                                      (float*)d_out);
    }
}

// round 17
// speedup vs baseline: 1.1296x; 1.1296x over previous
#include <cuda_runtime.h>
#include <math.h>

// RZ_50259707298063: y_re[s,b] = xr[s,b]*cos(phi_s) - xi[s,b]*sin(phi_s)
// phi_s = sum_i ( bit(s, nwires-1-i) ? +theta_i/2 : -theta_i/2 )
// Output = float32 real part (established round 7).
//
// R15: stream speed is invariant (~7us) across all configs; the win left is
// killing the 2nd launch. Single kernel, R10's best stream shape
// (1 float4/thread, grid=2048), with a ~15-instruction per-warp phase:
// lane i<nwires contributes +-angle[i]/2, shfl_xor butterfly reduce,
// __sincosf (2 MUFU). No smem, no barrier, no table.

__global__ void __launch_bounds__(256) rz_onepass(
    const float4* __restrict__ xr,
    const float4* __restrict__ xi,
    const float* __restrict__ angle,
    int nwires, int log2_vpr, int nvec,
    float4* __restrict__ out)
{
    const int v = blockIdx.x * blockDim.x + threadIdx.x;
    if (v >= nvec) return;

    // Bulk loads first: in flight during the phase computation.
    const float4 r  = xr[v];
    const float4 im = xi[v];

    const int s = v >> log2_vpr;           // warp-uniform (vpr >= 32)
    const int lane = threadIdx.x & 31;

    // Lane i (< nwires) contributes the signed half-angle for wire i.
    float contrib = 0.0f;
    if (lane < nwires) {
        const float half = 0.5f * __ldg(&angle[lane]);   // 1 LDG per warp
        contrib = ((s >> (nwires - 1 - lane)) & 1) ? half : -half;
    }
#pragma unroll
    for (int off = 16; off; off >>= 1)
        contrib += __shfl_xor_sync(0xffffffffu, contrib, off);

    float sn, cs;
    __sincosf(contrib, &sn, &cs);          // fast MUFU path (~2^-21 abs err)

    float4 o;
    o.x = fmaf(r.x, cs, -im.x * sn);
    o.y = fmaf(r.y, cs, -im.y * sn);
    o.z = fmaf(r.z, cs, -im.z * sn);
    o.w = fmaf(r.w, cs, -im.w * sn);
    out[v] = o;
}

// Generic fallback (proven correct round 7).
__global__ void __launch_bounds__(256) rz_real_scalar(
    const float* __restrict__ xr,
    const float* __restrict__ xi,
    const float* __restrict__ angle,
    int nwires, int batch, long n,
    float* __restrict__ out)
{
    const long stride = (long)gridDim.x * blockDim.x;
    for (long e = (long)blockIdx.x * blockDim.x + threadIdx.x; e < n; e += stride) {
        const long s = e / batch;
        float phi = 0.0f;
        for (int i = 0; i < nwires; i++) {
            const float half = 0.5f * __ldg(&angle[i]);
            phi += (((s >> (nwires - 1 - i)) & 1L) != 0) ? half : -half;
        }
        float sn, cs;
        sincosf(phi, &sn, &cs);
        out[e] = fmaf(xr[e], cs, -xi[e] * sn);
    }
}

extern "C" void kernel_launch(void* const* d_in, const int* in_sizes, int n_in,
                              void* d_out, int out_size) {
    if (n_in < 3 || d_out == nullptr) return;

    // angle = smallest buffer; remaining two equal-size buffers, in index
    // order, are x_real then x_imag.
    int ai = 0;
    for (int i = 1; i < n_in; i++)
        if (in_sizes[i] < in_sizes[ai]) ai = i;

    const float* angle = (const float*)d_in[ai];
    const float* xr = nullptr;
    const float* xi = nullptr;
    long nelem = 0;
    for (int i = 0; i < n_in; i++) {
        if (i == ai) continue;
        if (xr == nullptr) { xr = (const float*)d_in[i]; nelem = in_sizes[i]; }
        else if (xi == nullptr && in_sizes[i] == (int)nelem)
            xi = (const float*)d_in[i];
    }
    if (!angle || !xr || !xi || nelem <= 0) return;

    int nwires = in_sizes[ai];
    if (nwires > 20) { nwires /= 4; nelem /= 4; }   // byte-count hedge
    if (nwires < 1 || nwires > 20) return;

    const long nstates = 1L << nwires;
    int batch = (int)(nelem / nstates);
    if (batch <= 0) batch = 1;

    // Output budget in floats (real part only).
    long n = nelem;
    if ((long)out_size < n) n = (long)out_size;

    // Fast path: vpr = batch/4 a power of two and >= 32 (warp-uniform row).
    const int vpr = batch / 4;
    int log2_vpr = 0;
    while ((1 << log2_vpr) < vpr && log2_vpr < 30) log2_vpr++;

    const bool fused_ok =
        (n == nelem) && (batch % 4 == 0) && ((1 << log2_vpr) == vpr) &&
        (vpr >= 32) && (n / 4 < (1L << 31));

    if (fused_ok) {
        const int nvec = (int)(n / 4);
        rz_onepass<<<(nvec + 255) / 256, 256>>>(
            (const float4*)xr, (const float4*)xi, angle,
            nwires, log2_vpr, nvec, (float4*)d_out);
    } else {
        rz_real_scalar<<<2048, 256>>>(xr, xi, angle, nwires, batch, n,
                                      (float*)d_out);
    }
}